// round 10
// baseline (speedup 1.0000x reference)
#include <cuda_runtime.h>
#include <stdint.h>

#define NMAX 8192
#define WORDS 256          /* NMAX/32 */
#define EC    256          /* max entries per row (clamped) */
#define SLICES 16
#define W_IMG 1920.0f
#define H_IMG 1080.0f

// ---------------- device scratch ----------------
__device__ int g_rankp[SLICES][NMAX];
__device__ uint4 g_e8[NMAX];                  // first 8 earlier-neighbor cols (u16 x8), coalesced
__device__ uint16_t g_ecol[NMAX][EC];         // overflow entries (pos >= 8)
__device__ int g_ecnt[NMAX];
__device__ float4 g_abox[NMAX];               // clipped x1,y1,x2+1,y2+1
__device__ float4 g_obox[NMAX];               // clipped x1,y1,x2,y2
__device__ float g_s[NMAX], g_area[NMAX], g_by2[NMAX];
__device__ uint32_t g_head[WORDS];
__device__ int g_cluster[NMAX];
__device__ int g_cnt[NMAX];
__device__ float g_prob[NMAX];
__device__ unsigned long long g_pick[NMAX];   // (y2bits<<32) | (n - j)
__device__ int g_nm;

__device__ __forceinline__ unsigned long long skey(const float* __restrict__ s, int i)
{
    return (((unsigned long long)(~__float_as_uint(s[i]))) << 32) | (uint32_t)i;
}

// ---------------- K1: O(n^2) partial rank, 512-key tiles, 2 keys/thread --------
__global__ void __launch_bounds__(256) k_rank(const float* __restrict__ scores, int n)
{
    __shared__ unsigned long long sk[512];
    int base = blockIdx.y * 512;
    for (int t = threadIdx.x; t < 512; t += 256)
        sk[t] = (base + t < n) ? skey(scores, base + t) : 0xFFFFFFFFFFFFFFFFULL;
    __syncthreads();
    int i0 = blockIdx.x * 512 + threadIdx.x;
    int i1 = i0 + 256;
    unsigned long long a0 = (i0 < n) ? skey(scores, i0) : 0ULL;
    unsigned long long a1 = (i1 < n) ? skey(scores, i1) : 0ULL;
    int c0 = 0, c1 = 0;
    #pragma unroll 8
    for (int q = 0; q < 512; q++) {
        unsigned long long v = sk[q];
        c0 += (v < a0); c1 += (v < a1);
    }
    if (i0 < n) g_rankp[blockIdx.y][i0] = c0;
    if (i1 < n) g_rankp[blockIdx.y][i1] = c1;
}

// ---------------- K2: scatter into sorted order + per-index init ---------------
__global__ void k_gather(const float* __restrict__ boxes, const float* __restrict__ scores,
                         const void* __restrict__ nmp, int n, int slices)
{
    int i = blockIdx.x * blockDim.x + threadIdx.x;
    if (i >= n) return;
    int r = 0;
    for (int k = 0; k < slices; k++) r += g_rankp[k][i];
    float4 bx = ((const float4*)boxes)[i];
    float x1 = fminf(fmaxf(bx.x, 0.0f), W_IMG);
    float y1 = fminf(fmaxf(bx.y, 0.0f), H_IMG);
    float x2 = fminf(fmaxf(bx.z, 0.0f), W_IMG);
    float y2 = fminf(fmaxf(bx.w, 0.0f), H_IMG);
    g_obox[r] = make_float4(x1, y1, x2, y2);
    g_abox[r] = make_float4(x1, y1, x2 + 1.0f, y2 + 1.0f);
    g_by2[r] = y2;
    g_s[r] = scores[i];
    g_area[r] = ((x2 - x1) + 1.0f) * ((y2 - y1) + 1.0f);
    g_ecnt[i] = 0; g_cnt[i] = 0; g_prob[i] = 0.0f; g_pick[i] = 0ULL;
    if (i == 0) {
        int iv = ((const int*)nmp)[0];
        float fv = ((const float*)nmp)[0];
        g_nm = (iv > 0 && iv < 1000000) ? iv : (int)fv;
    }
}

// ---------------- K3: lower-triangle adjacency -> per-row col lists ------------
// tile = 64 rows x 512 cols; 256 threads (8 warps x 8 rows)
__global__ void __launch_bounds__(256) k_adj(int n)
{
    int rem = blockIdx.x, rt = 0;
    for (;;) { int cnt = (rt >> 3) + 1; if (rem < cnt) break; rem -= cnt; rt++; }
    int rowBase = rt * 64, colBase = rem * 512;

    __shared__ float4 cb[512]; __shared__ float ca[512];
    __shared__ float4 rb[64];  __shared__ float ra[64];

    for (int t = threadIdx.x; t < 512; t += 256) {
        int c = colBase + t;
        if (c < n) { cb[t] = g_abox[c]; ca[t] = g_area[c]; }
        else       { cb[t] = make_float4(2e9f, 2e9f, -2e9f, -2e9f); ca[t] = 1.0f; }
    }
    for (int t = threadIdx.x; t < 64; t += 256) {
        int r = rowBase + t; if (r >= n) r = n - 1;
        rb[t] = g_abox[r]; ra[t] = g_area[r];
    }
    __syncthreads();

    int warp = threadIdx.x >> 5, lane = threadIdx.x & 31;
    int rl0 = warp * 8;

    for (int grp = 0; grp < 2; grp++) {
        int rl = rl0 + grp * 4;
        float4 A[4]; float aa[4];
        #pragma unroll
        for (int k = 0; k < 4; k++) { A[k] = rb[rl + k]; aa[k] = ra[rl + k]; }
        int row0 = rowBase + rl;
        for (int wi = 0; wi < 16; wi++) {
            int cwb = colBase + wi * 32;
            if (cwb > row0 + 3) continue;              // fully above diagonal (warp-uniform)
            float4 B = cb[wi * 32 + lane];
            float ab = ca[wi * 32 + lane];
            #pragma unroll
            for (int k = 0; k < 4; k++) {
                int row = row0 + k;
                if (cwb > row || row >= n) continue;   // warp-uniform
                float w = fmaxf(fminf(A[k].z, B.z) - fmaxf(A[k].x, B.x), 0.0f);
                float h = fminf(A[k].w, B.w) - fmaxf(A[k].y, B.y);   // sign-safe: w>=0
                float inter = w * h;
                float den = (aa[k] + ab) - inter;
                unsigned bits = __ballot_sync(0xffffffffu, inter + inter > den);
                int d = row - cwb;
                if (d < 32) bits &= (1u << d) - 1u;    // strictly below row
                if (lane == 0 && bits) {
                    while (bits) {
                        int b = __ffs(bits) - 1; bits &= bits - 1;
                        int pos = atomicAdd(&g_ecnt[row], 1);
                        uint16_t col = (uint16_t)(cwb + b);
                        if (pos < 8) ((uint16_t*)&g_e8[row])[pos] = col;
                        else if (pos < EC) g_ecol[row][pos] = col;
                    }
                }
            }
        }
    }
}

// ---------------- K4: head fixed point, edges register-resident ----------------
__global__ void __launch_bounds__(1024) k_scan(int n)
{
    __shared__ uint2 bm[WORDS];               // x = head bits, y = decided bits
    int tid = threadIdx.x;
    if (tid < WORDS) bm[tid] = make_uint2(0u, 0u);
    __syncthreads();                          // init visible before any atomics

    // load: 8 rows per thread, fully coalesced
    uint4 e[8];
    uint32_t cpack = 0;       // 4-bit min(cnt,8) per row
    uint32_t ovf = 0;         // rows with cnt > 8
    uint32_t undec = 0;       // undecided row mask
    #pragma unroll
    for (int k = 0; k < 8; k++) {
        int j = tid + (k << 10);
        int cnt = (j < n) ? g_ecnt[j] : 0;
        e[k] = make_uint4(0u, 0u, 0u, 0u);
        if (j < n && cnt > 0) {
            e[k] = g_e8[j];
            int c8 = cnt < 8 ? cnt : 8;
            cpack |= (uint32_t)c8 << (k * 4);
            if (cnt > 8) ovf |= 1u << k;
            undec |= 1u << k;
        } else if (j < n) {
            atomicOr(&bm[j >> 5].x, 1u << (j & 31));   // head
            atomicOr(&bm[j >> 5].y, 1u << (j & 31));   // decided
        }
    }

    // uniform-exit fixed point: barrier-OR decides continuation for ALL threads
    while (__syncthreads_or((int)undec)) {
        #pragma unroll
        for (int k = 0; k < 8; k++) {
            if (!(undec & (1u << k))) continue;
            int j = tid + (k << 10);
            int c8 = (int)((cpack >> (k * 4)) & 15u);
            uint32_t cw[4] = {e[k].x, e[k].y, e[k].z, e[k].w};
            bool anyhead = false, alldec = true;
            #pragma unroll
            for (int q = 0; q < 8; q++) {
                if (q >= c8) break;
                int col = (q & 1) ? (int)(cw[q >> 1] >> 16) : (int)(cw[q >> 1] & 0xffffu);
                uint2 v = bm[col >> 5];
                uint32_t m = 1u << (col & 31);
                anyhead |= (v.x & m) != 0u;
                alldec  &= (v.y & m) != 0u;
            }
            if (!anyhead && (ovf & (1u << k))) {
                int ec = g_ecnt[j]; if (ec > EC) ec = EC;
                for (int q = 8; q < ec; q++) {
                    int col = (int)g_ecol[j][q];
                    uint32_t m = 1u << (col & 31);
                    if (bm[col >> 5].x & m) { anyhead = true; break; }
                    if (!(bm[col >> 5].y & m)) alldec = false;
                }
            }
            if (anyhead) {
                atomicOr(&bm[j >> 5].y, 1u << (j & 31));           // dead
                undec &= ~(1u << k);
            } else if (alldec) {
                atomicOr(&bm[j >> 5].x, 1u << (j & 31));           // head
                atomicOr(&bm[j >> 5].y, 1u << (j & 31));
                undec &= ~(1u << k);
            }
        }
    }
    if (tid < WORDS) g_head[tid] = bm[tid].x;
}

// ---------------- K5: cluster assignment + all segment reductions --------------
__global__ void k_assign(int n)
{
    __shared__ uint32_t hh[WORDS];
    for (int t = threadIdx.x; t < WORDS; t += blockDim.x) hh[t] = g_head[t];
    __syncthreads();
    int j = blockIdx.x * blockDim.x + threadIdx.x;
    if (j >= n) return;
    int cnt = g_ecnt[j]; if (cnt > EC) cnt = EC;
    int best = 0x7fffffff;
    uint4 ev = g_e8[j];
    uint32_t cw[4] = {ev.x, ev.y, ev.z, ev.w};
    int r8 = cnt < 8 ? cnt : 8;
    #pragma unroll
    for (int q = 0; q < 8; q++) {
        if (q >= r8) break;
        int col = (q & 1) ? (int)(cw[q >> 1] >> 16) : (int)(cw[q >> 1] & 0xffffu);
        if ((hh[col >> 5] >> (col & 31)) & 1u) { if (col < best) best = col; }
    }
    for (int q = 8; q < cnt; q++) {
        int col = (int)g_ecol[j][q];
        if ((hh[col >> 5] >> (col & 31)) & 1u) { if (col < best) best = col; }
    }
    int cf = (best == 0x7fffffff) ? j : best;
    g_cluster[j] = cf;
    atomicAdd(&g_cnt[cf], 1);
    atomicAdd(&g_prob[cf], g_s[j]);
    unsigned long long key = (((unsigned long long)__float_as_uint(g_by2[j])) << 32)
                           | (unsigned long long)(uint32_t)(n - j);
    atomicMax(&g_pick[cf], key);
}

// ---------------- K6: write output ----------------------------------------------
__global__ void k_out(float* __restrict__ out, int n, int out_size)
{
    int i = blockIdx.x * blockDim.x + threadIdx.x;
    if (i < n) {
        int c = g_cluster[i];
        float nmf = (float)g_nm;
        int firstj = n - (int)(uint32_t)(g_pick[c] & 0xffffffffULL);
        bool keep = (i == firstj) && ((float)g_cnt[c] >= nmf / 3.0f);
        float so = g_prob[c] / nmf;
        float4 b = g_obox[i];
        out[i * 5 + 0] = keep ? b.x : 0.0f;
        out[i * 5 + 1] = keep ? b.y : 0.0f;
        out[i * 5 + 2] = keep ? b.z : 0.0f;
        out[i * 5 + 3] = keep ? b.w : 0.0f;
        out[i * 5 + 4] = keep ? so : 0.0f;
        if (out_size >= 6 * n) out[5 * n + i] = keep ? 1.0f : 0.0f;
    }
    int stride = gridDim.x * blockDim.x;
    for (int t = 6 * n + i; t < out_size; t += stride) out[t] = 0.0f;
}

// ---------------- launcher -------------------------------------------------------
extern "C" void kernel_launch(void* const* d_in, const int* in_sizes, int n_in,
                              void* d_out, int out_size)
{
    const float* boxes  = (const float*)d_in[0];
    const float* scores = (const float*)d_in[1];
    const void*  nmp    = d_in[2];
    int n = in_sizes[1];
    if (n > NMAX) n = NMAX;

    int nb = (n + 255) / 256;
    int slices = (n + 511) / 512;            // <= SLICES
    dim3 rg((n + 511) / 512, slices);
    k_rank<<<rg, 256>>>(scores, n);
    k_gather<<<nb, 256>>>(boxes, scores, nmp, n, slices);

    int rowTiles = (n + 63) / 64;
    int tiles = 0;
    for (int rt = 0; rt < rowTiles; rt++) tiles += (rt >> 3) + 1;
    k_adj<<<tiles, 256>>>(n);

    k_scan<<<1, 1024>>>(n);
    k_assign<<<nb, 256>>>(n);
    k_out<<<nb, 256>>>((float*)d_out, n, out_size);
}

// round 11
// speedup vs baseline: 1.2069x; 1.2069x over previous
#include <cuda_runtime.h>
#include <stdint.h>

#define NMAX 8192
#define WORDS 256          /* NMAX/32 */
#define EC    256          /* max entries per row (clamped) */
#define SLICES 16
#define W_IMG 1920.0f
#define H_IMG 1080.0f

// ---------------- device scratch ----------------
__device__ int g_rankp[SLICES][NMAX];
__device__ uint4 g_e8[NMAX];                  // first 8 earlier-neighbor cols (u16 x8), coalesced
__device__ uint16_t g_ecol[NMAX][EC];         // overflow entries (pos >= 8)
__device__ int g_ecnt[NMAX];
__device__ float4 g_abox[NMAX];               // clipped x1,y1,x2+1,y2+1
__device__ float4 g_obox[NMAX];               // clipped x1,y1,x2,y2
__device__ float g_s[NMAX], g_area[NMAX], g_by2[NMAX];
__device__ uint32_t g_head[WORDS];
__device__ int g_cluster[NMAX];
__device__ int g_cnt[NMAX];
__device__ float g_prob[NMAX];
__device__ unsigned long long g_pick[NMAX];   // (y2bits<<32) | (n - j)
__device__ int g_nm;

__device__ __forceinline__ unsigned long long skey(const float* __restrict__ s, int i)
{
    return (((unsigned long long)(~__float_as_uint(s[i]))) << 32) | (uint32_t)i;
}

// ---------------- K1: O(n^2) partial rank, 512-key tiles, 2 keys/thread --------
__global__ void __launch_bounds__(256) k_rank(const float* __restrict__ scores, int n)
{
    __shared__ unsigned long long sk[512];
    int base = blockIdx.y * 512;
    for (int t = threadIdx.x; t < 512; t += 256)
        sk[t] = (base + t < n) ? skey(scores, base + t) : 0xFFFFFFFFFFFFFFFFULL;
    __syncthreads();
    int i0 = blockIdx.x * 512 + threadIdx.x;
    int i1 = i0 + 256;
    unsigned long long a0 = (i0 < n) ? skey(scores, i0) : 0ULL;
    unsigned long long a1 = (i1 < n) ? skey(scores, i1) : 0ULL;
    int c0 = 0, c1 = 0;
    #pragma unroll 8
    for (int q = 0; q < 512; q++) {
        unsigned long long v = sk[q];
        c0 += (v < a0); c1 += (v < a1);
    }
    if (i0 < n) g_rankp[blockIdx.y][i0] = c0;
    if (i1 < n) g_rankp[blockIdx.y][i1] = c1;
}

// ---------------- K2: scatter into sorted order + per-index init ---------------
__global__ void k_gather(const float* __restrict__ boxes, const float* __restrict__ scores,
                         const void* __restrict__ nmp, int n, int slices)
{
    int i = blockIdx.x * blockDim.x + threadIdx.x;
    if (i >= n) return;
    int r = 0;
    for (int k = 0; k < slices; k++) r += g_rankp[k][i];
    float4 bx = ((const float4*)boxes)[i];
    float x1 = fminf(fmaxf(bx.x, 0.0f), W_IMG);
    float y1 = fminf(fmaxf(bx.y, 0.0f), H_IMG);
    float x2 = fminf(fmaxf(bx.z, 0.0f), W_IMG);
    float y2 = fminf(fmaxf(bx.w, 0.0f), H_IMG);
    g_obox[r] = make_float4(x1, y1, x2, y2);
    g_abox[r] = make_float4(x1, y1, x2 + 1.0f, y2 + 1.0f);
    g_by2[r] = y2;
    g_s[r] = scores[i];
    g_area[r] = ((x2 - x1) + 1.0f) * ((y2 - y1) + 1.0f);
    g_ecnt[i] = 0; g_cnt[i] = 0; g_prob[i] = 0.0f; g_pick[i] = 0ULL;
    if (i == 0) {
        int iv = ((const int*)nmp)[0];
        float fv = ((const float*)nmp)[0];
        g_nm = (iv > 0 && iv < 1000000) ? iv : (int)fv;
    }
}

// ---------------- K3: lower-triangle adjacency -> per-row col lists ------------
// tile = 64 rows x 512 cols; 256 threads (8 warps x 8 rows)
__global__ void __launch_bounds__(256) k_adj(int n)
{
    int rem = blockIdx.x, rt = 0;
    for (;;) { int cnt = (rt >> 3) + 1; if (rem < cnt) break; rem -= cnt; rt++; }
    int rowBase = rt * 64, colBase = rem * 512;

    __shared__ float4 cb[512]; __shared__ float ca[512];
    __shared__ float4 rb[64];  __shared__ float ra[64];

    for (int t = threadIdx.x; t < 512; t += 256) {
        int c = colBase + t;
        if (c < n) { cb[t] = g_abox[c]; ca[t] = g_area[c]; }
        else       { cb[t] = make_float4(2e9f, 2e9f, -2e9f, -2e9f); ca[t] = 1.0f; }
    }
    for (int t = threadIdx.x; t < 64; t += 256) {
        int r = rowBase + t; if (r >= n) r = n - 1;
        rb[t] = g_abox[r]; ra[t] = g_area[r];
    }
    __syncthreads();

    int warp = threadIdx.x >> 5, lane = threadIdx.x & 31;
    int rl0 = warp * 8;

    for (int grp = 0; grp < 2; grp++) {
        int rl = rl0 + grp * 4;
        float4 A[4]; float aa[4];
        #pragma unroll
        for (int k = 0; k < 4; k++) { A[k] = rb[rl + k]; aa[k] = ra[rl + k]; }
        int row0 = rowBase + rl;
        for (int wi = 0; wi < 16; wi++) {
            int cwb = colBase + wi * 32;
            if (cwb > row0 + 3) continue;              // fully above diagonal (warp-uniform)
            float4 B = cb[wi * 32 + lane];
            float ab = ca[wi * 32 + lane];
            #pragma unroll
            for (int k = 0; k < 4; k++) {
                int row = row0 + k;
                if (cwb > row || row >= n) continue;   // warp-uniform
                float w = fmaxf(fminf(A[k].z, B.z) - fmaxf(A[k].x, B.x), 0.0f);
                float h = fminf(A[k].w, B.w) - fmaxf(A[k].y, B.y);   // sign-safe: w>=0
                float inter = w * h;
                float den = (aa[k] + ab) - inter;
                unsigned bits = __ballot_sync(0xffffffffu, inter + inter > den);
                int d = row - cwb;
                if (d < 32) bits &= (1u << d) - 1u;    // strictly below row
                if (lane == 0 && bits) {
                    while (bits) {
                        int b = __ffs(bits) - 1; bits &= bits - 1;
                        int pos = atomicAdd(&g_ecnt[row], 1);
                        uint16_t col = (uint16_t)(cwb + b);
                        if (pos < 8) ((uint16_t*)&g_e8[row])[pos] = col;
                        else if (pos < EC) g_ecol[row][pos] = col;
                    }
                }
            }
        }
    }
}

// ---------------- K4: worklist fixed point, uint4 edge loads -------------------
__global__ void __launch_bounds__(1024) k_scan(int n)
{
    __shared__ uint32_t headb[WORDS];
    __shared__ uint32_t decb[WORDS];          // decided = head | dead
    __shared__ uint8_t  scnt[NMAX];           // min(cnt,255), filled pass 0
    __shared__ uint16_t wl[2][NMAX];          // 32 KB
    __shared__ int wcnt[2];

    int tid = threadIdx.x, lane = tid & 31;
    for (int t = tid; t < WORDS; t += 1024) { headb[t] = 0u; decb[t] = 0u; }
    if (tid < 2) wcnt[tid] = 0;
    __syncthreads();

    // pass 0: rows with no earlier neighbors are heads; rest -> worklist
    for (int j0 = tid; j0 < ((n + 31) & ~31); j0 += 1024) {
        bool hasrow = (j0 < n);
        int cnt = hasrow ? g_ecnt[j0] : 0;
        if (hasrow) scnt[j0] = (uint8_t)(cnt < 255 ? cnt : 255);
        bool work = hasrow && (cnt > 0);
        if (hasrow && cnt == 0) {
            atomicOr(&headb[j0 >> 5], 1u << (j0 & 31));
            atomicOr(&decb[j0 >> 5], 1u << (j0 & 31));
        }
        unsigned wb = __ballot_sync(0xffffffffu, work);
        if (work) {
            int leader = __ffs(wb) - 1;
            int basep = 0;
            if (lane == leader) basep = atomicAdd(&wcnt[0], __popc(wb));
            basep = __shfl_sync(wb, basep, leader);
            int off = __popc(wb & ((1u << lane) - 1u));
            wl[0][basep + off] = (uint16_t)j0;
        }
    }
    __syncthreads();

    int cur = 0;
    for (int pass = 0; pass < NMAX && wcnt[cur] > 0; pass++) {
        int cnt_cur = wcnt[cur];
        int nxt = cur ^ 1;
        for (int q = tid; q < cnt_cur; q += 1024) {
            int j = wl[cur][q];
            int sc = (int)scnt[j];
            int c8 = sc < 8 ? sc : 8;
            uint4 ev = g_e8[j];                        // one 16-B load, L2-hot
            uint32_t cw[4] = {ev.x, ev.y, ev.z, ev.w};
            bool anyhead = false, alldec = true;
            #pragma unroll
            for (int e = 0; e < 8; e++) {
                if (e >= c8) break;
                int col = (e & 1) ? (int)(cw[e >> 1] >> 16) : (int)(cw[e >> 1] & 0xffffu);
                uint32_t m = 1u << (col & 31);
                anyhead |= (headb[col >> 5] & m) != 0u;
                alldec  &= (decb[col >> 5] & m) != 0u;
            }
            if (!anyhead && sc > 8) {
                int ec = g_ecnt[j]; if (ec > EC) ec = EC;
                for (int e = 8; e < ec; e++) {
                    int col = (int)g_ecol[j][e];
                    uint32_t m = 1u << (col & 31);
                    if (headb[col >> 5] & m) { anyhead = true; break; }
                    if (!(decb[col >> 5] & m)) alldec = false;
                }
            }
            if (anyhead) atomicOr(&decb[j >> 5], 1u << (j & 31));            // dead
            else if (alldec) {
                atomicOr(&headb[j >> 5], 1u << (j & 31));
                atomicOr(&decb[j >> 5], 1u << (j & 31));
            }
            else { int p = atomicAdd(&wcnt[nxt], 1); wl[nxt][p] = (uint16_t)j; }
        }
        __syncthreads();
        if (tid == 0) wcnt[cur] = 0;
        cur = nxt;
        __syncthreads();
    }
    for (int t = tid; t < WORDS; t += 1024) g_head[t] = headb[t];
}

// ---------------- K5: cluster assignment + all segment reductions --------------
__global__ void k_assign(int n)
{
    __shared__ uint32_t hh[WORDS];
    for (int t = threadIdx.x; t < WORDS; t += blockDim.x) hh[t] = g_head[t];
    __syncthreads();
    int j = blockIdx.x * blockDim.x + threadIdx.x;
    if (j >= n) return;
    int cnt = g_ecnt[j]; if (cnt > EC) cnt = EC;
    int best = 0x7fffffff;
    uint4 ev = g_e8[j];
    uint32_t cw[4] = {ev.x, ev.y, ev.z, ev.w};
    int r8 = cnt < 8 ? cnt : 8;
    #pragma unroll
    for (int q = 0; q < 8; q++) {
        if (q >= r8) break;
        int col = (q & 1) ? (int)(cw[q >> 1] >> 16) : (int)(cw[q >> 1] & 0xffffu);
        if ((hh[col >> 5] >> (col & 31)) & 1u) { if (col < best) best = col; }
    }
    for (int q = 8; q < cnt; q++) {
        int col = (int)g_ecol[j][q];
        if ((hh[col >> 5] >> (col & 31)) & 1u) { if (col < best) best = col; }
    }
    int cf = (best == 0x7fffffff) ? j : best;
    g_cluster[j] = cf;
    atomicAdd(&g_cnt[cf], 1);
    atomicAdd(&g_prob[cf], g_s[j]);
    unsigned long long key = (((unsigned long long)__float_as_uint(g_by2[j])) << 32)
                           | (unsigned long long)(uint32_t)(n - j);
    atomicMax(&g_pick[cf], key);
}

// ---------------- K6: write output ----------------------------------------------
__global__ void k_out(float* __restrict__ out, int n, int out_size)
{
    int i = blockIdx.x * blockDim.x + threadIdx.x;
    if (i < n) {
        int c = g_cluster[i];
        float nmf = (float)g_nm;
        int firstj = n - (int)(uint32_t)(g_pick[c] & 0xffffffffULL);
        bool keep = (i == firstj) && ((float)g_cnt[c] >= nmf / 3.0f);
        float so = g_prob[c] / nmf;
        float4 b = g_obox[i];
        out[i * 5 + 0] = keep ? b.x : 0.0f;
        out[i * 5 + 1] = keep ? b.y : 0.0f;
        out[i * 5 + 2] = keep ? b.z : 0.0f;
        out[i * 5 + 3] = keep ? b.w : 0.0f;
        out[i * 5 + 4] = keep ? so : 0.0f;
        if (out_size >= 6 * n) out[5 * n + i] = keep ? 1.0f : 0.0f;
    }
    int stride = gridDim.x * blockDim.x;
    for (int t = 6 * n + i; t < out_size; t += stride) out[t] = 0.0f;
}

// ---------------- launcher -------------------------------------------------------
extern "C" void kernel_launch(void* const* d_in, const int* in_sizes, int n_in,
                              void* d_out, int out_size)
{
    const float* boxes  = (const float*)d_in[0];
    const float* scores = (const float*)d_in[1];
    const void*  nmp    = d_in[2];
    int n = in_sizes[1];
    if (n > NMAX) n = NMAX;

    int nb = (n + 255) / 256;
    int slices = (n + 511) / 512;            // <= SLICES
    dim3 rg((n + 511) / 512, slices);
    k_rank<<<rg, 256>>>(scores, n);
    k_gather<<<nb, 256>>>(boxes, scores, nmp, n, slices);

    int rowTiles = (n + 63) / 64;
    int tiles = 0;
    for (int rt = 0; rt < rowTiles; rt++) tiles += (rt >> 3) + 1;
    k_adj<<<tiles, 256>>>(n);

    k_scan<<<1, 1024>>>(n);
    k_assign<<<nb, 256>>>(n);
    k_out<<<nb, 256>>>((float*)d_out, n, out_size);
}

// round 12
// speedup vs baseline: 1.2887x; 1.0678x over previous
#include <cuda_runtime.h>
#include <stdint.h>

#define NMAX 8192
#define WORDS 256          /* NMAX/32 */
#define EC    256          /* max entries per row (clamped) */
#define SLICES 16
#define W_IMG 1920.0f
#define H_IMG 1080.0f

// ---------------- device scratch ----------------
__device__ int g_rankp[SLICES][NMAX];
__device__ uint4 g_e8[NMAX];                  // first 8 earlier-neighbor cols (u16 x8), coalesced
__device__ uint16_t g_ecol[NMAX][EC];         // overflow entries (pos >= 8)
__device__ int g_ecnt[NMAX];
__device__ float4 g_abox[NMAX];               // clipped x1,y1,x2+1,y2+1
__device__ float4 g_obox[NMAX];               // clipped x1,y1,x2,y2
__device__ float g_s[NMAX], g_area[NMAX], g_by2[NMAX];
__device__ uint32_t g_head[WORDS];
__device__ int g_cluster[NMAX];
__device__ int g_cnt[NMAX];
__device__ float g_prob[NMAX];
__device__ unsigned long long g_pick[NMAX];   // (y2bits<<32) | (n - j)
__device__ int g_nm;

__device__ __forceinline__ unsigned long long skey(const float* __restrict__ s, int i)
{
    return (((unsigned long long)(~__float_as_uint(s[i]))) << 32) | (uint32_t)i;
}

// ---------------- K1: O(n^2) partial rank, 512-key tiles, 2 keys/thread --------
__global__ void __launch_bounds__(256) k_rank(const float* __restrict__ scores, int n)
{
    __shared__ unsigned long long sk[512];
    int base = blockIdx.y * 512;
    for (int t = threadIdx.x; t < 512; t += 256)
        sk[t] = (base + t < n) ? skey(scores, base + t) : 0xFFFFFFFFFFFFFFFFULL;
    __syncthreads();
    int i0 = blockIdx.x * 512 + threadIdx.x;
    int i1 = i0 + 256;
    unsigned long long a0 = (i0 < n) ? skey(scores, i0) : 0ULL;
    unsigned long long a1 = (i1 < n) ? skey(scores, i1) : 0ULL;
    int c0 = 0, c1 = 0;
    #pragma unroll 8
    for (int q = 0; q < 512; q++) {
        unsigned long long v = sk[q];
        c0 += (v < a0); c1 += (v < a1);
    }
    if (i0 < n) g_rankp[blockIdx.y][i0] = c0;
    if (i1 < n) g_rankp[blockIdx.y][i1] = c1;
}

// ---------------- K2: scatter into sorted order + per-index init ---------------
__global__ void k_gather(const float* __restrict__ boxes, const float* __restrict__ scores,
                         const void* __restrict__ nmp, int n, int slices)
{
    int i = blockIdx.x * blockDim.x + threadIdx.x;
    if (i >= n) return;
    int r = 0;
    for (int k = 0; k < slices; k++) r += g_rankp[k][i];
    float4 bx = ((const float4*)boxes)[i];
    float x1 = fminf(fmaxf(bx.x, 0.0f), W_IMG);
    float y1 = fminf(fmaxf(bx.y, 0.0f), H_IMG);
    float x2 = fminf(fmaxf(bx.z, 0.0f), W_IMG);
    float y2 = fminf(fmaxf(bx.w, 0.0f), H_IMG);
    g_obox[r] = make_float4(x1, y1, x2, y2);
    g_abox[r] = make_float4(x1, y1, x2 + 1.0f, y2 + 1.0f);
    g_by2[r] = y2;
    g_s[r] = scores[i];
    g_area[r] = ((x2 - x1) + 1.0f) * ((y2 - y1) + 1.0f);
    g_ecnt[i] = 0; g_cnt[i] = 0; g_prob[i] = 0.0f; g_pick[i] = 0ULL;
    if (i == 0) {
        int iv = ((const int*)nmp)[0];
        float fv = ((const float*)nmp)[0];
        g_nm = (iv > 0 && iv < 1000000) ? iv : (int)fv;
    }
}

// ---------------- K3: lower-triangle adjacency -> per-row col lists ------------
// tile = 64 rows x 512 cols; 256 threads = 8 warps x 8 rows (register-resident)
__global__ void __launch_bounds__(256) k_adj(int n)
{
    int rem = blockIdx.x, rt = 0;
    for (;;) { int cnt = (rt >> 3) + 1; if (rem < cnt) break; rem -= cnt; rt++; }
    int rowBase = rt * 64, colBase = rem * 512;

    __shared__ float4 cb[512]; __shared__ float ca[512];
    __shared__ float4 rb[64];  __shared__ float ra[64];

    for (int t = threadIdx.x; t < 512; t += 256) {
        int c = colBase + t;
        if (c < n) { cb[t] = g_abox[c]; ca[t] = g_area[c]; }
        else       { cb[t] = make_float4(2e9f, 2e9f, -2e9f, -2e9f); ca[t] = 1.0f; }
    }
    for (int t = threadIdx.x; t < 64; t += 256) {
        int r = rowBase + t; if (r >= n) r = n - 1;
        rb[t] = g_abox[r]; ra[t] = g_area[r];
    }
    __syncthreads();

    int warp = threadIdx.x >> 5, lane = threadIdx.x & 31;
    int row0 = rowBase + warp * 8;

    float4 A[8]; float aa[8];
    #pragma unroll
    for (int k = 0; k < 8; k++) { A[k] = rb[warp * 8 + k]; aa[k] = ra[warp * 8 + k]; }

    for (int wi = 0; wi < 16; wi++) {
        int cwb = colBase + wi * 32;
        if (cwb > row0 + 7) continue;                  // above all 8 rows (warp-uniform)
        float4 B = cb[wi * 32 + lane];
        float ab = ca[wi * 32 + lane];
        #pragma unroll
        for (int k = 0; k < 8; k++) {
            int row = row0 + k;
            if (cwb > row || row >= n) continue;       // warp-uniform
            float w = fmaxf(fminf(A[k].z, B.z) - fmaxf(A[k].x, B.x), 0.0f);
            float h = fminf(A[k].w, B.w) - fmaxf(A[k].y, B.y);
            float inter = w * h;
            // 2*inter > (aa+ab)-inter  <=>  3*inter > aa+ab  (real arithmetic)
            unsigned bits = __ballot_sync(0xffffffffu, 3.0f * inter > aa[k] + ab);
            int d = row - cwb;
            if (d < 32) bits &= (1u << d) - 1u;        // strictly below row
            if (bits) {                                 // warp-uniform
                int basep = 0;
                if (lane == 0) basep = atomicAdd(&g_ecnt[row], __popc(bits));
                basep = __shfl_sync(0xffffffffu, basep, 0);
                if ((bits >> lane) & 1u) {
                    int pos = basep + __popc(bits & ((1u << lane) - 1u));
                    uint16_t col = (uint16_t)(cwb + lane);
                    if (pos < 8) ((uint16_t*)&g_e8[row])[pos] = col;
                    else if (pos < EC) g_ecol[row][pos] = col;
                }
            }
        }
    }
}

// ---------------- K4: chunk-sequential local fixed point (1 row/thread) --------
__global__ void __launch_bounds__(1024) k_scan(int n)
{
    __shared__ uint32_t headb[WORDS];
    __shared__ uint32_t decb[WORDS];          // decided = head | dead
    int tid = threadIdx.x;
    if (tid < WORDS) { headb[tid] = 0u; decb[tid] = 0u; }
    __syncthreads();

    int chunks = (n + 1023) >> 10;
    for (int c = 0; c < chunks; c++) {
        int base = c << 10;
        int j = base + tid;
        bool isrow = (j < n);
        int cnt = isrow ? g_ecnt[j] : 0;
        uint4 ev = make_uint4(0u, 0u, 0u, 0u);
        if (isrow && cnt > 0) ev = g_e8[j];
        uint32_t cw[4] = {ev.x, ev.y, ev.z, ev.w};
        int c8 = cnt < 8 ? cnt : 8;
        bool ovf = cnt > 8;
        int ecl = cnt < EC ? cnt : EC;

        // overflow ext precompute: cross-chunk edges are final; test heads once
        bool ovfExtAny = false;
        if (ovf) {
            for (int e = 8; e < ecl; e++) {
                int col = (int)g_ecol[j][e];
                if (col < base && ((headb[col >> 5] >> (col & 31)) & 1u)) { ovfExtAny = true; break; }
            }
        }

        if (isrow && cnt == 0) {
            atomicOr(&headb[j >> 5], 1u << (j & 31));
            atomicOr(&decb[j >> 5], 1u << (j & 31));
        }
        bool undec = isrow && (cnt > 0);

        // local fixed point; earlier chunks final, in-chunk edges converge
        for (int p = 0; p < 1025 && __syncthreads_or((int)undec); p++) {
            if (undec) {
                bool anyhead = ovfExtAny, alldec = true;
                #pragma unroll
                for (int e = 0; e < 8; e++) {
                    if (e >= c8) break;
                    int col = (e & 1) ? (int)(cw[e >> 1] >> 16) : (int)(cw[e >> 1] & 0xffffu);
                    uint32_t m = 1u << (col & 31);
                    anyhead |= (headb[col >> 5] & m) != 0u;
                    alldec  &= (decb[col >> 5] & m) != 0u;
                }
                if (!anyhead && ovf) {
                    for (int e = 8; e < ecl; e++) {
                        int col = (int)g_ecol[j][e];
                        if (col < base) continue;      // folded into ovfExtAny / decided
                        uint32_t m = 1u << (col & 31);
                        if (headb[col >> 5] & m) { anyhead = true; break; }
                        if (!(decb[col >> 5] & m)) alldec = false;
                    }
                }
                if (anyhead) {
                    atomicOr(&decb[j >> 5], 1u << (j & 31));           // dead
                    undec = false;
                } else if (alldec) {
                    atomicOr(&headb[j >> 5], 1u << (j & 31));          // head
                    atomicOr(&decb[j >> 5], 1u << (j & 31));
                    undec = false;
                }
            }
        }
    }
    if (tid < WORDS) g_head[tid] = headb[tid];
}

// ---------------- K5: cluster assignment + all segment reductions --------------
__global__ void k_assign(int n)
{
    __shared__ uint32_t hh[WORDS];
    for (int t = threadIdx.x; t < WORDS; t += blockDim.x) hh[t] = g_head[t];
    __syncthreads();
    int j = blockIdx.x * blockDim.x + threadIdx.x;
    if (j >= n) return;
    int cnt = g_ecnt[j]; if (cnt > EC) cnt = EC;
    int best = 0x7fffffff;
    uint4 ev = g_e8[j];
    uint32_t cw[4] = {ev.x, ev.y, ev.z, ev.w};
    int r8 = cnt < 8 ? cnt : 8;
    #pragma unroll
    for (int q = 0; q < 8; q++) {
        if (q >= r8) break;
        int col = (q & 1) ? (int)(cw[q >> 1] >> 16) : (int)(cw[q >> 1] & 0xffffu);
        if ((hh[col >> 5] >> (col & 31)) & 1u) { if (col < best) best = col; }
    }
    for (int q = 8; q < cnt; q++) {
        int col = (int)g_ecol[j][q];
        if ((hh[col >> 5] >> (col & 31)) & 1u) { if (col < best) best = col; }
    }
    int cf = (best == 0x7fffffff) ? j : best;
    g_cluster[j] = cf;
    atomicAdd(&g_cnt[cf], 1);
    atomicAdd(&g_prob[cf], g_s[j]);
    unsigned long long key = (((unsigned long long)__float_as_uint(g_by2[j])) << 32)
                           | (unsigned long long)(uint32_t)(n - j);
    atomicMax(&g_pick[cf], key);
}

// ---------------- K6: write output ----------------------------------------------
__global__ void k_out(float* __restrict__ out, int n, int out_size)
{
    int i = blockIdx.x * blockDim.x + threadIdx.x;
    if (i < n) {
        int c = g_cluster[i];
        float nmf = (float)g_nm;
        int firstj = n - (int)(uint32_t)(g_pick[c] & 0xffffffffULL);
        bool keep = (i == firstj) && ((float)g_cnt[c] >= nmf / 3.0f);
        float so = g_prob[c] / nmf;
        float4 b = g_obox[i];
        out[i * 5 + 0] = keep ? b.x : 0.0f;
        out[i * 5 + 1] = keep ? b.y : 0.0f;
        out[i * 5 + 2] = keep ? b.z : 0.0f;
        out[i * 5 + 3] = keep ? b.w : 0.0f;
        out[i * 5 + 4] = keep ? so : 0.0f;
        if (out_size >= 6 * n) out[5 * n + i] = keep ? 1.0f : 0.0f;
    }
    int stride = gridDim.x * blockDim.x;
    for (int t = 6 * n + i; t < out_size; t += stride) out[t] = 0.0f;
}

// ---------------- launcher -------------------------------------------------------
extern "C" void kernel_launch(void* const* d_in, const int* in_sizes, int n_in,
                              void* d_out, int out_size)
{
    const float* boxes  = (const float*)d_in[0];
    const float* scores = (const float*)d_in[1];
    const void*  nmp    = d_in[2];
    int n = in_sizes[1];
    if (n > NMAX) n = NMAX;

    int nb = (n + 255) / 256;
    int slices = (n + 511) / 512;            // <= SLICES
    dim3 rg((n + 511) / 512, slices);
    k_rank<<<rg, 256>>>(scores, n);
    k_gather<<<nb, 256>>>(boxes, scores, nmp, n, slices);

    int rowTiles = (n + 63) / 64;
    int tiles = 0;
    for (int rt = 0; rt < rowTiles; rt++) tiles += (rt >> 3) + 1;
    k_adj<<<tiles, 256>>>(n);

    k_scan<<<1, 1024>>>(n);
    k_assign<<<nb, 256>>>(n);
    k_out<<<nb, 256>>>((float*)d_out, n, out_size);
}